// round 3
// baseline (speedup 1.0000x reference)
#include <cuda_runtime.h>
#include <math.h>

#define NB   262144
#define H1C  128
#define H2C  256
#define H3C  200
#define GC   25
#define DC   4
#define GDC  100

// Scratch (no allocations allowed) --------------------------------------
__device__ float g_h2 [(size_t)NB * H2C];   // trunk activations after layer 2
__device__ float g_h3 [(size_t)NB * H3C];   // trunk activations after layer 3
__device__ float g_W2T[H1C * H2C];          // W2 transposed: [k][n]
__device__ float g_W3T[H2C * H3C];          // W3 transposed: [k][n]
__device__ float g_WpT[H3C * GDC];          // Wpai transposed: [k][g*4+d]

// ------------------------------------------------------------------ prep
__global__ void k_prep(const float* __restrict__ W2,
                       const float* __restrict__ W3,
                       const float* __restrict__ Wp) {
    int stride = gridDim.x * blockDim.x;
    int i0 = blockIdx.x * blockDim.x + threadIdx.x;
    for (int e = i0; e < H1C * H2C; e += stride) {
        int k = e / H2C, n = e % H2C;
        g_W2T[e] = W2[n * H1C + k];
    }
    for (int e = i0; e < H2C * H3C; e += stride) {
        int k = e / H3C, n = e % H3C;
        g_W3T[e] = W3[n * H2C + k];
    }
    for (int e = i0; e < H3C * GDC; e += stride) {
        int k = e / GDC, gd = e % GDC;
        g_WpT[e] = Wp[gd * H3C + k];
    }
}

// ------------------------------------------------- layer1+layer2 (fused)
// 64 rows per block, 256 threads, 8x8 register tiles over 64x256 output.
// W2 staged in two 64-k panels (64KB each) -> 96KB smem -> 2 CTAs/SM.
__global__ __launch_bounds__(256) void k_l12(const float* __restrict__ x0,
                                             const float* __restrict__ W1,
                                             const float* __restrict__ b1,
                                             const float* __restrict__ b2) {
    extern __shared__ float sm[];
    float* h1s = sm;                 // [64][128]   32KB
    float* W2s = sm + 64 * H1C;      // [64][256]   64KB panel (k-major)
    __shared__ float W1s[H1C * 3];
    __shared__ float b1s[H1C];
    __shared__ float b2s[H2C];
    __shared__ float xs[64 * 3];

    const int tid = threadIdx.x;
    const int b0  = blockIdx.x * 64;

    for (int e = tid; e < H1C * 3; e += 256) W1s[e] = W1[e];
    if (tid < H1C) b1s[tid] = b1[tid];
    b2s[tid] = b2[tid];
    for (int e = tid; e < 64 * 3; e += 256) xs[e] = x0[(size_t)b0 * 3 + e];
    __syncthreads();

    // layer 1: h1 = relu(x0 @ W1^T + b1)   (fan-in 3, trivial)
    for (int e = tid; e < 64 * H1C; e += 256) {
        int r = e >> 7, j = e & 127;
        float v = fmaf(xs[r * 3 + 0], W1s[j * 3 + 0],
                  fmaf(xs[r * 3 + 1], W1s[j * 3 + 1],
                  fmaf(xs[r * 3 + 2], W1s[j * 3 + 2], b1s[j])));
        h1s[e] = fmaxf(v, 0.f);
    }

    // layer 2 GEMM: [64 x 256], K = 128 in two 64-k panels
    const int tx = tid & 31, ty = tid >> 5;
    const int r0 = ty * 8, c0 = tx * 8;
    float acc[8][8];
#pragma unroll
    for (int i = 0; i < 8; i++)
#pragma unroll
        for (int j = 0; j < 8; j++) acc[i][j] = 0.f;

    for (int p = 0; p < 2; p++) {
        __syncthreads();     // protects h1s (first iter) / W2s reuse (later)
        {
            float4* dst = (float4*)W2s;
            const float4* src = (const float4*)(g_W2T + p * 64 * H2C);
            for (int e = tid; e < 64 * H2C / 4; e += 256) dst[e] = src[e];
        }
        __syncthreads();
        const int kb = p * 64;
        for (int k = 0; k < 64; k += 4) {
            float4 a[8];
#pragma unroll
            for (int i = 0; i < 8; i++)
                a[i] = *(const float4*)(h1s + (r0 + i) * H1C + kb + k);
#pragma unroll
            for (int kk = 0; kk < 4; kk++) {
                float4 bv0 = *(const float4*)(W2s + (k + kk) * H2C + c0);
                float4 bv1 = *(const float4*)(W2s + (k + kk) * H2C + c0 + 4);
                float bv[8] = {bv0.x, bv0.y, bv0.z, bv0.w,
                               bv1.x, bv1.y, bv1.z, bv1.w};
#pragma unroll
                for (int i = 0; i < 8; i++) {
                    float av = kk == 0 ? a[i].x : kk == 1 ? a[i].y
                             : kk == 2 ? a[i].z : a[i].w;
#pragma unroll
                    for (int j = 0; j < 8; j++)
                        acc[i][j] = fmaf(av, bv[j], acc[i][j]);
                }
            }
        }
    }

#pragma unroll
    for (int i = 0; i < 8; i++) {
        float o[8];
#pragma unroll
        for (int j = 0; j < 8; j++)
            o[j] = fmaxf(acc[i][j] + b2s[c0 + j], 0.f);
        float* dst = g_h2 + (size_t)(b0 + r0 + i) * H2C + c0;
        *(float4*)dst       = make_float4(o[0], o[1], o[2], o[3]);
        *(float4*)(dst + 4) = make_float4(o[4], o[5], o[6], o[7]);
    }
}

// --------------------------------------------------------------- layer3
// 128 rows per block, 400 threads (16 row-thr x 25 col-thr), 8x8 tiles,
// K=256 in four 64-k panels. All lanes active.
__global__ __launch_bounds__(400) void k_l3(const float* __restrict__ b3) {
    extern __shared__ float sm[];
    float* h2s = sm;                 // [128][256]  128KB
    float* W3s = sm + 128 * H2C;     // [64][200]   50KB panel (k-major)
    __shared__ float b3s[H3C];

    const int tid = threadIdx.x;
    const int b0  = blockIdx.x * 128;

    for (int e = tid; e < H3C; e += 400) b3s[e] = b3[e];
    {
        float4* dst = (float4*)h2s;
        const float4* src = (const float4*)(g_h2 + (size_t)b0 * H2C);
        for (int e = tid; e < 128 * H2C / 4; e += 400) dst[e] = src[e];
    }

    const int ct = tid % 25, rt = tid / 25;   // rt in [0,16)
    const int r0 = rt * 8, c0 = ct * 8;
    float acc[8][8];
#pragma unroll
    for (int i = 0; i < 8; i++)
#pragma unroll
        for (int j = 0; j < 8; j++) acc[i][j] = 0.f;

    for (int p = 0; p < 4; p++) {
        __syncthreads();   // covers h2s staging (p=0) and W3s reuse
        {
            float4* dst = (float4*)W3s;
            const float4* src = (const float4*)(g_W3T + p * 64 * H3C);
            for (int e = tid; e < 64 * H3C / 4; e += 400) dst[e] = src[e];
        }
        __syncthreads();
        const int kb = p * 64;
        for (int k = 0; k < 64; k += 4) {
            float4 a[8];
#pragma unroll
            for (int i = 0; i < 8; i++)
                a[i] = *(const float4*)(h2s + (r0 + i) * H2C + kb + k);
#pragma unroll
            for (int kk = 0; kk < 4; kk++) {
                float4 bv0 = *(const float4*)(W3s + (k + kk) * H3C + c0);
                float4 bv1 = *(const float4*)(W3s + (k + kk) * H3C + c0 + 4);
                float bv[8] = {bv0.x, bv0.y, bv0.z, bv0.w,
                               bv1.x, bv1.y, bv1.z, bv1.w};
#pragma unroll
                for (int i = 0; i < 8; i++) {
                    float av = kk == 0 ? a[i].x : kk == 1 ? a[i].y
                             : kk == 2 ? a[i].z : a[i].w;
#pragma unroll
                    for (int j = 0; j < 8; j++)
                        acc[i][j] = fmaf(av, bv[j], acc[i][j]);
                }
            }
        }
    }

#pragma unroll
    for (int i = 0; i < 8; i++) {
        float o[8];
#pragma unroll
        for (int j = 0; j < 8; j++)
            o[j] = fmaxf(acc[i][j] + b3s[c0 + j], 0.f);
        float* dst = g_h3 + (size_t)(b0 + r0 + i) * H3C + c0;
        *(float4*)dst       = make_float4(o[0], o[1], o[2], o[3]);
        *(float4*)(dst + 4) = make_float4(o[4], o[5], o[6], o[7]);
    }
}

// ------------------------------------------- heads + gumbel-argmax + out
// 64 rows per block, 256 threads. Wp in 40-k panels -> ~93KB smem -> 2 CTA/SM.
// pi GEMM uses contiguous threads 0..199 (8 row-thr x 25 col-thr).
// Selection: one thread per (row,d), Wmu/Wsig from L2 (80KB tables).
__global__ __launch_bounds__(256) void k_heads(
        const float* __restrict__ gumbel, const float* __restrict__ rnd,
        const float* __restrict__ Wmu,  const float* __restrict__ bmu,
        const float* __restrict__ Wsig, const float* __restrict__ bsig,
        const float* __restrict__ bpai, float* __restrict__ out) {
    extern __shared__ float sm[];
    float* h3s = sm;                    // [64][200]  51200B
    float* Wps = sm + 64 * H3C;         // [40][100]  16000B panel (k-major)
    float* lps = Wps + 40 * GDC;        // [64][100]  25600B  log(pi+eps)
    __shared__ float bps[GDC];

    const int tid = threadIdx.x;
    const int b0  = blockIdx.x * 64;

    for (int e = tid; e < GDC; e += 256) bps[e] = bpai[e];
    {
        float4* dst = (float4*)h3s;
        const float4* src = (const float4*)(g_h3 + (size_t)b0 * H3C);
        for (int e = tid; e < 64 * H3C / 4; e += 256) dst[e] = src[e];
    }

    // pi GEMM: [64 x 100], K = 200 in five 40-k panels.
    // threads 0..199 active: ct = tid/8 (g index), rt = tid%8; 8x4 tiles.
    const int rt = tid & 7, ct = tid >> 3;
    const int r0 = rt * 8, c0 = ct * 4;
    const bool act = (ct < 25);
    float acc[8][4];
#pragma unroll
    for (int i = 0; i < 8; i++)
#pragma unroll
        for (int j = 0; j < 4; j++) acc[i][j] = 0.f;

    for (int p = 0; p < 5; p++) {
        __syncthreads();   // covers h3s staging (p=0) and Wps reuse
        {
            float4* dst = (float4*)Wps;
            const float4* src = (const float4*)(g_WpT + p * 40 * GDC);
            for (int e = tid; e < 40 * GDC / 4; e += 256) dst[e] = src[e];
        }
        __syncthreads();
        if (act) {
            const int kb = p * 40;
            for (int k = 0; k < 40; k += 4) {
                float4 a[8];
#pragma unroll
                for (int i = 0; i < 8; i++)
                    a[i] = *(const float4*)(h3s + (r0 + i) * H3C + kb + k);
#pragma unroll
                for (int kk = 0; kk < 4; kk++) {
                    float4 bv = *(const float4*)(Wps + (k + kk) * GDC + c0);
#pragma unroll
                    for (int i = 0; i < 8; i++) {
                        float av = kk == 0 ? a[i].x : kk == 1 ? a[i].y
                                 : kk == 2 ? a[i].z : a[i].w;
                        acc[i][0] = fmaf(av, bv.x, acc[i][0]);
                        acc[i][1] = fmaf(av, bv.y, acc[i][1]);
                        acc[i][2] = fmaf(av, bv.z, acc[i][2]);
                        acc[i][3] = fmaf(av, bv.w, acc[i][3]);
                    }
                }
            }
        }
    }
    if (act) {
#pragma unroll
        for (int i = 0; i < 8; i++)
#pragma unroll
            for (int j = 0; j < 4; j++) {
                int gd = c0 + j;
                float pai = fabsf(acc[i][j] + bps[gd]);
                lps[(r0 + i) * GDC + gd] = logf(pai + 1e-12f);
            }
    }
    __syncthreads();

    // Gumbel-argmax + selected mu/sigma + output: one thread per (row, d).
    {
        const int r = tid >> 2, d = tid & 3;
        const float* gp = gumbel + (size_t)(b0 + r) * GDC + d;
        float best = -1e30f;
        int bg = 0;
#pragma unroll
        for (int g = 0; g < GC; g++) {
            float v = lps[r * GDC + g * 4 + d] + gp[g * 4];
            if (v > best) { best = v; bg = g; }
        }
        const int head = bg * 4 + d;

        const float4* wm = (const float4*)(Wmu  + (size_t)head * H3C);
        const float4* ws = (const float4*)(Wsig + (size_t)head * H3C);
        const float4* hv = (const float4*)(h3s + r * H3C);
        float smu = 0.f, ssg = 0.f;
#pragma unroll 5
        for (int i = 0; i < 50; i++) {
            float4 h = hv[i];
            float4 m = wm[i];
            float4 s = ws[i];
            smu = fmaf(h.x, m.x, fmaf(h.y, m.y, fmaf(h.z, m.z, fmaf(h.w, m.w, smu))));
            ssg = fmaf(h.x, s.x, fmaf(h.y, s.y, fmaf(h.z, s.z, fmaf(h.w, s.w, ssg))));
        }
        float mu = smu + bmu[head];
        float sg = fabsf(ssg + bsig[head]);
        size_t oi = (size_t)(b0 + r) * DC + d;
        out[oi] = rnd[oi] * sg + mu;
    }
}

// ---------------------------------------------------------------- launch
extern "C" void kernel_launch(void* const* d_in, const int* in_sizes, int n_in,
                              void* d_out, int out_size) {
    const float* x0   = (const float*)d_in[0];
    const float* rnd  = (const float*)d_in[1];
    const float* gum  = (const float*)d_in[2];
    const float* W1   = (const float*)d_in[3];
    const float* b1   = (const float*)d_in[4];
    const float* W2   = (const float*)d_in[5];
    const float* b2   = (const float*)d_in[6];
    const float* W3   = (const float*)d_in[7];
    const float* b3   = (const float*)d_in[8];
    const float* Wmu  = (const float*)d_in[9];
    const float* bmu  = (const float*)d_in[10];
    const float* Wsig = (const float*)d_in[11];
    const float* bsig = (const float*)d_in[12];
    const float* Wpai = (const float*)d_in[13];
    const float* bpai = (const float*)d_in[14];
    float* out = (float*)d_out;

    const size_t smA = (size_t)(64 * H1C + 64 * H2C) * sizeof(float);          // 96KB
    const size_t smB = (size_t)(128 * H2C + 64 * H3C) * sizeof(float);         // 178KB
    const size_t smC = (size_t)(64 * H3C + 40 * GDC + 64 * GDC) * sizeof(float); // ~93KB

    cudaFuncSetAttribute(k_l12,   cudaFuncAttributeMaxDynamicSharedMemorySize, (int)smA);
    cudaFuncSetAttribute(k_l3,    cudaFuncAttributeMaxDynamicSharedMemorySize, (int)smB);
    cudaFuncSetAttribute(k_heads, cudaFuncAttributeMaxDynamicSharedMemorySize, (int)smC);

    k_prep <<<64, 256>>>(W2, W3, Wpai);
    k_l12  <<<NB / 64, 256, smA>>>(x0, W1, b1, b2);
    k_l3   <<<NB / 128, 400, smB>>>(b3);
    k_heads<<<NB / 64, 256, smC>>>(gum, rnd, Wmu, bmu, Wsig, bsig, bpai, out);
}

// round 5
// speedup vs baseline: 1.0271x; 1.0271x over previous
#include <cuda_runtime.h>
#include <math.h>
#include <stdint.h>

#define NB   262144
#define H1C  128
#define H2C  256
#define H3C  200
#define GC   25
#define DC   4
#define GDC  100

// ---------------------------------------------------------- device scratch
__device__ float g_h2h[(size_t)NB * H2C];   // h2 tf32-hi split
__device__ float g_h2l[(size_t)NB * H2C];   // h2 tf32-lo split
__device__ float g_h3 [(size_t)NB * H3C];
__device__ float g_WpT[H3C * GDC];
// W2 panels: [panel 0..3][split 0..1][k 0..127][n 0..71 (64 data + 8 pad)]
__device__ float g_W2P[4 * 2 * 128 * 72];
// W3 panels: [kp 0..1][np 0..4][split 0..1][kk 0..127][nn 0..39]
__device__ float g_W3P[2 * 5 * 2 * 128 * 40];

// ------------------------------------------------------------- tf32 helpers
__device__ __forceinline__ uint32_t f2tf32(float x) {
    uint32_t r;
    asm("cvt.rna.tf32.f32 %0, %1;" : "=r"(r) : "f"(x));
    return r;
}
__device__ __forceinline__ void split_tf32(float x, float& hi, float& lo) {
    hi = __uint_as_float(f2tf32(x));
    lo = __uint_as_float(f2tf32(x - hi));
}
// D += A*B  (m16n8k8, tf32 inputs as b32 regs, f32 accumulate)
__device__ __forceinline__ void mma8(float* c, uint32_t a0, uint32_t a1,
                                     uint32_t a2, uint32_t a3,
                                     uint32_t b0, uint32_t b1) {
    asm volatile(
        "mma.sync.aligned.m16n8k8.row.col.f32.tf32.tf32.f32 "
        "{%0,%1,%2,%3}, {%4,%5,%6,%7}, {%8,%9}, {%0,%1,%2,%3};"
        : "+f"(c[0]), "+f"(c[1]), "+f"(c[2]), "+f"(c[3])
        : "r"(a0), "r"(a1), "r"(a2), "r"(a3), "r"(b0), "r"(b1));
}

// ------------------------------------------------------------------- prep
__global__ void k_prep(const float* __restrict__ W2, const float* __restrict__ W3,
                       const float* __restrict__ Wp) {
    int t = blockIdx.x * blockDim.x + threadIdx.x;
    int S = gridDim.x * blockDim.x;
    // W2 panels (tf32 split, n-padded 64->72)
    for (int e = t; e < 4 * 2 * 128 * 72; e += S) {
        int nn = e % 72, k = (e / 72) & 127;
        int s = (e / (72 * 128)) & 1, p = e / (72 * 128 * 2);
        float v = 0.f;
        if (nn < 64) {
            float x = W2[(64 * p + nn) * H1C + k];
            float hi, lo; split_tf32(x, hi, lo);
            v = s ? lo : hi;
        }
        g_W2P[e] = v;
    }
    // W3 panels
    for (int e = t; e < 2 * 5 * 2 * 128 * 40; e += S) {
        int nn = e % 40, kk = (e / 40) & 127;
        int s = (e / 5120) & 1, np = (e / 10240) % 5, kp = e / 51200;
        float x = W3[(40 * np + nn) * H2C + 128 * kp + kk];
        float hi, lo; split_tf32(x, hi, lo);
        g_W3P[e] = s ? lo : hi;
    }
    for (int e = t; e < H3C * GDC; e += S) {
        int k = e / GDC, gd = e % GDC;
        g_WpT[e] = Wp[gd * H3C + k];
    }
}

// ----------------------------------------------- layer1 + layer2 (mma tf32)
// 128 rows/CTA, 256 thr (8 warps, 16 rows each).
// smem: A1h[128][132], A1l[128][132] (66KB+66KB), B[2][128][72] (72KB).
#define AW 132
__global__ __launch_bounds__(256) void k_l12(const float* __restrict__ x0,
                                             const float* __restrict__ W1,
                                             const float* __restrict__ b1,
                                             const float* __restrict__ b2) {
    extern __shared__ float sm[];
    float* Ah = sm;                    // [128][132]
    float* Al = sm + 128 * AW;         // [128][132]
    float* Bs = sm + 2 * 128 * AW;     // [2][128][72]
    __shared__ float xs[128 * 3], W1s[H1C * 3], b1s[H1C], b2s[H2C];

    const int tid = threadIdx.x;
    const int b0  = blockIdx.x * 128;
    const int w   = tid >> 5, lane = tid & 31;
    const int gid = lane >> 2, tig = lane & 3;
    const int r0  = w * 16;

    for (int e = tid; e < H1C * 3; e += 256) W1s[e] = W1[e];
    if (tid < H1C) b1s[tid] = b1[tid];
    b2s[tid] = b2[tid];
    for (int e = tid; e < 128 * 3; e += 256) xs[e] = x0[(size_t)b0 * 3 + e];
    __syncthreads();

    // layer 1 -> tf32 split into A buffers
    for (int e = tid; e < 128 * H1C; e += 256) {
        int r = e >> 7, k = e & 127;
        float v = fmaf(xs[r * 3 + 0], W1s[k * 3 + 0],
                  fmaf(xs[r * 3 + 1], W1s[k * 3 + 1],
                  fmaf(xs[r * 3 + 2], W1s[k * 3 + 2], b1s[k])));
        v = fmaxf(v, 0.f);
        float hi, lo; split_tf32(v, hi, lo);
        Ah[r * AW + k] = hi;
        Al[r * AW + k] = lo;
    }

    for (int p = 0; p < 4; p++) {
        __syncthreads();   // A ready (p=0) / previous mma done before B reuse
        {
            float4* dst = (float4*)Bs;
            const float4* src = (const float4*)(g_W2P + p * 2 * 128 * 72);
            for (int e = tid; e < 2 * 128 * 72 / 4; e += 256) dst[e] = src[e];
        }
        __syncthreads();

        float acc[8][4];
#pragma unroll
        for (int t = 0; t < 8; t++)
#pragma unroll
            for (int j = 0; j < 4; j++) acc[t][j] = 0.f;

#pragma unroll 4
        for (int ks = 0; ks < 16; ks++) {
            const int kk = ks * 8;
            const float* ar0 = Ah + (r0 + gid) * AW + kk + tig;
            const float* ar8 = Ah + (r0 + gid + 8) * AW + kk + tig;
            const float* br0 = Al + (r0 + gid) * AW + kk + tig;
            const float* br8 = Al + (r0 + gid + 8) * AW + kk + tig;
            uint32_t ah0 = __float_as_uint(ar0[0]), ah1 = __float_as_uint(ar8[0]);
            uint32_t ah2 = __float_as_uint(ar0[4]), ah3 = __float_as_uint(ar8[4]);
            uint32_t al0 = __float_as_uint(br0[0]), al1 = __float_as_uint(br8[0]);
            uint32_t al2 = __float_as_uint(br0[4]), al3 = __float_as_uint(br8[4]);
            const float* bh = Bs + (kk + tig) * 72 + gid;
            const float* bl = bh + 128 * 72;
#pragma unroll
            for (int t = 0; t < 8; t++) {
                uint32_t bh0 = __float_as_uint(bh[8 * t]);
                uint32_t bh1 = __float_as_uint(bh[8 * t + 4 * 72]);
                uint32_t bl0 = __float_as_uint(bl[8 * t]);
                uint32_t bl1 = __float_as_uint(bl[8 * t + 4 * 72]);
                mma8(acc[t], ah0, ah1, ah2, ah3, bh0, bh1);
                mma8(acc[t], ah0, ah1, ah2, ah3, bl0, bl1);
                mma8(acc[t], al0, al1, al2, al3, bh0, bh1);
            }
        }

        // epilogue: h2 = relu(acc + b2) -> split -> gmem
#pragma unroll
        for (int t = 0; t < 8; t++) {
            int n = 64 * p + 8 * t + 2 * tig;
            float v0 = fmaxf(acc[t][0] + b2s[n],     0.f);
            float v1 = fmaxf(acc[t][1] + b2s[n + 1], 0.f);
            float v2 = fmaxf(acc[t][2] + b2s[n],     0.f);
            float v3 = fmaxf(acc[t][3] + b2s[n + 1], 0.f);
            float h0, l0, h1, l1, h2v, l2, h3v, l3;
            split_tf32(v0, h0, l0); split_tf32(v1, h1, l1);
            split_tf32(v2, h2v, l2); split_tf32(v3, h3v, l3);
            size_t rA = (size_t)(b0 + r0 + gid) * H2C + n;
            size_t rB = (size_t)(b0 + r0 + gid + 8) * H2C + n;
            *(float2*)(g_h2h + rA) = make_float2(h0, h1);
            *(float2*)(g_h2l + rA) = make_float2(l0, l1);
            *(float2*)(g_h2h + rB) = make_float2(h2v, h3v);
            *(float2*)(g_h2l + rB) = make_float2(l2, l3);
        }
    }
}

// ------------------------------------------------------- layer3 (mma tf32)
// 128 rows/CTA, 256 thr. K=256 in 2 k-panels; N=200 in 5 n-panels of 40.
__global__ __launch_bounds__(256) void k_l3(const float* __restrict__ b3) {
    extern __shared__ float sm[];
    float* Ah = sm;                    // [128][132]
    float* Al = sm + 128 * AW;
    float* Bs = sm + 2 * 128 * AW;     // [2][128][40]
    __shared__ float b3s[H3C];

    const int tid = threadIdx.x;
    const int b0  = blockIdx.x * 128;
    const int w   = tid >> 5, lane = tid & 31;
    const int gid = lane >> 2, tig = lane & 3;
    const int r0  = w * 16;

    for (int e = tid; e < H3C; e += 256) b3s[e] = b3[e];

    float acc[25][4];
#pragma unroll
    for (int t = 0; t < 25; t++)
#pragma unroll
        for (int j = 0; j < 4; j++) acc[t][j] = 0.f;

    for (int kp = 0; kp < 2; kp++) {
        __syncthreads();   // previous mma done before A overwrite
        // stage h2 split k-panel: rows 0..127, cols 128*kp..+128
        for (int e = tid; e < 128 * 32; e += 256) {
            int r = e >> 5, c4 = (e & 31) * 4;
            size_t src = (size_t)(b0 + r) * H2C + 128 * kp + c4;
            *(float4*)(Ah + r * AW + c4) = *(const float4*)(g_h2h + src);
            *(float4*)(Al + r * AW + c4) = *(const float4*)(g_h2l + src);
        }
        for (int np = 0; np < 5; np++) {
            __syncthreads();   // A staged (np=0) / mma done before B reuse
            {
                float4* dst = (float4*)Bs;
                const float4* src = (const float4*)(g_W3P + (kp * 5 + np) * 2 * 128 * 40);
                for (int e = tid; e < 2 * 128 * 40 / 4; e += 256) dst[e] = src[e];
            }
            __syncthreads();
#pragma unroll 4
            for (int ks = 0; ks < 16; ks++) {
                const int kk = ks * 8;
                const float* ar0 = Ah + (r0 + gid) * AW + kk + tig;
                const float* ar8 = Ah + (r0 + gid + 8) * AW + kk + tig;
                const float* br0 = Al + (r0 + gid) * AW + kk + tig;
                const float* br8 = Al + (r0 + gid + 8) * AW + kk + tig;
                uint32_t ah0 = __float_as_uint(ar0[0]), ah1 = __float_as_uint(ar8[0]);
                uint32_t ah2 = __float_as_uint(ar0[4]), ah3 = __float_as_uint(ar8[4]);
                uint32_t al0 = __float_as_uint(br0[0]), al1 = __float_as_uint(br8[0]);
                uint32_t al2 = __float_as_uint(br0[4]), al3 = __float_as_uint(br8[4]);
                const float* bh = Bs + (kk + tig) * 40 + gid;
                const float* bl = bh + 128 * 40;
#pragma unroll
                for (int t = 0; t < 5; t++) {
                    uint32_t bh0 = __float_as_uint(bh[8 * t]);
                    uint32_t bh1 = __float_as_uint(bh[8 * t + 4 * 40]);
                    uint32_t bl0 = __float_as_uint(bl[8 * t]);
                    uint32_t bl1 = __float_as_uint(bl[8 * t + 4 * 40]);
                    float* c = acc[np * 5 + t];
                    mma8(c, ah0, ah1, ah2, ah3, bh0, bh1);
                    mma8(c, ah0, ah1, ah2, ah3, bl0, bl1);
                    mma8(c, al0, al1, al2, al3, bh0, bh1);
                }
            }
        }
    }

    // epilogue: h3 = relu(acc + b3) -> gmem
#pragma unroll
    for (int t = 0; t < 25; t++) {
        int n = 8 * t + 2 * tig;
        float v0 = fmaxf(acc[t][0] + b3s[n],     0.f);
        float v1 = fmaxf(acc[t][1] + b3s[n + 1], 0.f);
        float v2 = fmaxf(acc[t][2] + b3s[n],     0.f);
        float v3 = fmaxf(acc[t][3] + b3s[n + 1], 0.f);
        size_t rA = (size_t)(b0 + r0 + gid) * H3C + n;
        size_t rB = (size_t)(b0 + r0 + gid + 8) * H3C + n;
        *(float2*)(g_h3 + rA) = make_float2(v0, v1);
        *(float2*)(g_h3 + rB) = make_float2(v2, v3);
    }
}

// ------------------------------------------- heads + gumbel-argmax + out
__global__ __launch_bounds__(256) void k_heads(
        const float* __restrict__ gumbel, const float* __restrict__ rnd,
        const float* __restrict__ Wmu,  const float* __restrict__ bmu,
        const float* __restrict__ Wsig, const float* __restrict__ bsig,
        const float* __restrict__ bpai, float* __restrict__ out) {
    extern __shared__ float sm[];
    float* h3s = sm;                    // [64][200]
    float* Wps = sm + 64 * H3C;         // [40][100] panel
    float* lps = Wps + 40 * GDC;        // [64][100]
    __shared__ float bps[GDC];
    __shared__ int   idxs[256];

    const int tid = threadIdx.x;
    const int b0  = blockIdx.x * 64;

    for (int e = tid; e < GDC; e += 256) bps[e] = bpai[e];
    {
        float4* dst = (float4*)h3s;
        const float4* src = (const float4*)(g_h3 + (size_t)b0 * H3C);
        for (int e = tid; e < 64 * H3C / 4; e += 256) dst[e] = src[e];
    }

    // pi GEMM: [64 x 100], K=200 in five 40-k panels; threads 0..199 active
    const int rt = tid & 7, ct = tid >> 3;
    const int r0 = rt * 8, c0 = ct * 4;
    const bool act = (ct < 25);
    float acc[8][4];
#pragma unroll
    for (int i = 0; i < 8; i++)
#pragma unroll
        for (int j = 0; j < 4; j++) acc[i][j] = 0.f;

    for (int p = 0; p < 5; p++) {
        __syncthreads();
        {
            float4* dst = (float4*)Wps;
            const float4* src = (const float4*)(g_WpT + p * 40 * GDC);
            for (int e = tid; e < 40 * GDC / 4; e += 256) dst[e] = src[e];
        }
        __syncthreads();
        if (act) {
            const int kb = p * 40;
            for (int k = 0; k < 40; k += 4) {
                float4 a[8];
#pragma unroll
                for (int i = 0; i < 8; i++)
                    a[i] = *(const float4*)(h3s + (r0 + i) * H3C + kb + k);
#pragma unroll
                for (int kk = 0; kk < 4; kk++) {
                    float4 bv = *(const float4*)(Wps + (k + kk) * GDC + c0);
#pragma unroll
                    for (int i = 0; i < 8; i++) {
                        float av = kk == 0 ? a[i].x : kk == 1 ? a[i].y
                                 : kk == 2 ? a[i].z : a[i].w;
                        acc[i][0] = fmaf(av, bv.x, acc[i][0]);
                        acc[i][1] = fmaf(av, bv.y, acc[i][1]);
                        acc[i][2] = fmaf(av, bv.z, acc[i][2]);
                        acc[i][3] = fmaf(av, bv.w, acc[i][3]);
                    }
                }
            }
        }
    }
    if (act) {
#pragma unroll
        for (int i = 0; i < 8; i++)
#pragma unroll
            for (int j = 0; j < 4; j++) {
                int gd = c0 + j;
                float pai = fabsf(acc[i][j] + bps[gd]);
                lps[(r0 + i) * GDC + gd] = logf(pai + 1e-12f);
            }
    }
    __syncthreads();

    // Gumbel-argmax per (row, d)
    {
        int r = tid >> 2, d = tid & 3;
        const float* gp = gumbel + (size_t)(b0 + r) * GDC + d;
        float best = -1e30f;
        int bg = 0;
#pragma unroll
        for (int g = 0; g < GC; g++) {
            float v = lps[r * GDC + g * 4 + d] + gp[g * 4];
            if (v > best) { best = v; bg = g; }
        }
        idxs[tid] = bg;
    }
    __syncthreads();

    // Selected mu / sigma: warp-cooperative (coalesced row walks)
    const int wid = tid >> 5, lane = tid & 31;
    for (int q = 0; q < 32; q++) {
        int p = wid * 32 + q;
        int r = p >> 2, d = p & 3;
        int head = idxs[p] * 4 + d;
        const float4* wm = (const float4*)(Wmu  + (size_t)head * H3C);
        const float4* ws = (const float4*)(Wsig + (size_t)head * H3C);
        const float4* hv = (const float4*)(h3s + r * H3C);

        float4 h0 = hv[lane];
        float4 m0 = wm[lane];
        float4 s0 = ws[lane];
        float smu = h0.x * m0.x + h0.y * m0.y + h0.z * m0.z + h0.w * m0.w;
        float ssg = h0.x * s0.x + h0.y * s0.y + h0.z * s0.z + h0.w * s0.w;
        if (lane < 18) {
            float4 h1v = hv[32 + lane];
            float4 m1  = wm[32 + lane];
            float4 s1  = ws[32 + lane];
            smu += h1v.x * m1.x + h1v.y * m1.y + h1v.z * m1.z + h1v.w * m1.w;
            ssg += h1v.x * s1.x + h1v.y * s1.y + h1v.z * s1.z + h1v.w * s1.w;
        }
#pragma unroll
        for (int off = 16; off > 0; off >>= 1) {
            smu += __shfl_xor_sync(0xffffffffu, smu, off);
            ssg += __shfl_xor_sync(0xffffffffu, ssg, off);
        }
        if (lane == 0) {
            float mu = smu + bmu[head];
            float sg = fabsf(ssg + bsig[head]);
            size_t oi = (size_t)(b0 + r) * DC + d;
            out[oi] = rnd[oi] * sg + mu;
        }
    }
}

// ---------------------------------------------------------------- launch
extern "C" void kernel_launch(void* const* d_in, const int* in_sizes, int n_in,
                              void* d_out, int out_size) {
    const float* x0   = (const float*)d_in[0];
    const float* rnd  = (const float*)d_in[1];
    const float* gum  = (const float*)d_in[2];
    const float* W1   = (const float*)d_in[3];
    const float* b1   = (const float*)d_in[4];
    const float* W2   = (const float*)d_in[5];
    const float* b2   = (const float*)d_in[6];
    const float* W3   = (const float*)d_in[7];
    const float* b3   = (const float*)d_in[8];
    const float* Wmu  = (const float*)d_in[9];
    const float* bmu  = (const float*)d_in[10];
    const float* Wsig = (const float*)d_in[11];
    const float* bsig = (const float*)d_in[12];
    const float* Wpai = (const float*)d_in[13];
    const float* bpai = (const float*)d_in[14];
    float* out = (float*)d_out;

    const size_t smA = (size_t)(2 * 128 * AW + 2 * 128 * 72) * sizeof(float); // 208896B
    const size_t smB = (size_t)(2 * 128 * AW + 2 * 128 * 40) * sizeof(float); // 176128B
    const size_t smC = (size_t)(64 * H3C + 40 * GDC + 64 * GDC) * sizeof(float); // 92800B

    cudaFuncSetAttribute(k_l12,   cudaFuncAttributeMaxDynamicSharedMemorySize, (int)smA);
    cudaFuncSetAttribute(k_l3,    cudaFuncAttributeMaxDynamicSharedMemorySize, (int)smB);
    cudaFuncSetAttribute(k_heads, cudaFuncAttributeMaxDynamicSharedMemorySize, (int)smC);

    k_prep <<<128, 256>>>(W2, W3, Wpai);
    k_l12  <<<NB / 128, 256, smA>>>(x0, W1, b1, b2);
    k_l3   <<<NB / 128, 256, smB>>>(b3);
    k_heads<<<NB / 64, 256, smC>>>(gum, rnd, Wmu, bmu, Wsig, bsig, bpai, out);
}

// round 6
// speedup vs baseline: 1.0630x; 1.0349x over previous
#include <cuda_runtime.h>
#include <math.h>
#include <stdint.h>

#define NB   262144
#define H1C  128
#define H2C  256
#define H3C  200
#define GC   25
#define DC   4
#define GDC  100

// ---------------------------------------------------------- device scratch
__device__ float g_h2 [(size_t)NB * H2C];   // h2 fp32
__device__ float g_h3 [(size_t)NB * H3C];
__device__ float g_WpT[H3C * GDC];
// fragment-ordered tf32-split weights:
// W2F: [p(4)][ks(16)][t(8)][s(2)][lane(32)] float2   (65536 floats)
__device__ float2 g_W2F[4 * 16 * 8 * 2 * 32];
// W3F: [kc(4)][ks(8)][t(25)][s(2)][lane(32)] float2  (102400 floats)
__device__ float2 g_W3F[4 * 8 * 25 * 2 * 32];

// ------------------------------------------------------------- tf32 helpers
__device__ __forceinline__ uint32_t f2tf32(float x) {
    uint32_t r;
    asm("cvt.rna.tf32.f32 %0, %1;" : "=r"(r) : "f"(x));
    return r;
}
__device__ __forceinline__ void split_tf32(float x, float& hi, float& lo) {
    hi = __uint_as_float(f2tf32(x));
    lo = __uint_as_float(f2tf32(x - hi));
}
__device__ __forceinline__ void mma8(float* c, uint32_t a0, uint32_t a1,
                                     uint32_t a2, uint32_t a3,
                                     uint32_t b0, uint32_t b1) {
    asm volatile(
        "mma.sync.aligned.m16n8k8.row.col.f32.tf32.tf32.f32 "
        "{%0,%1,%2,%3}, {%4,%5,%6,%7}, {%8,%9}, {%0,%1,%2,%3};"
        : "+f"(c[0]), "+f"(c[1]), "+f"(c[2]), "+f"(c[3])
        : "r"(a0), "r"(a1), "r"(a2), "r"(a3), "r"(b0), "r"(b1));
}
// A-fragment scatter slot/lane for element (rr in 0..15, kk in 0..7)
__device__ __forceinline__ void frag_pos(int rr, int kk, int& lane, int& slot) {
    lane = ((rr & 7) << 2) | (kk & 3);
    slot = ((kk & 4) ? 2 : 0) + ((rr & 8) ? 1 : 0);
}

// ------------------------------------------------------------------- prep
__global__ void k_prep(const float* __restrict__ W2, const float* __restrict__ W3,
                       const float* __restrict__ Wp) {
    int t0 = blockIdx.x * blockDim.x + threadIdx.x;
    int S  = gridDim.x * blockDim.x;
    // W2F
    for (int i = t0; i < 4 * 16 * 8 * 2 * 32; i += S) {
        int lane = i & 31, s = (i >> 5) & 1, t = (i >> 6) & 7;
        int ks = (i >> 9) & 15, p = i >> 13;
        int gid = lane >> 2, tig = lane & 3;
        int n = 64 * p + 8 * t + gid;
        int k0 = 8 * ks + tig;
        float h0, l0, h1, l1;
        split_tf32(W2[n * H1C + k0],     h0, l0);
        split_tf32(W2[n * H1C + k0 + 4], h1, l1);
        g_W2F[i] = s ? make_float2(l0, l1) : make_float2(h0, h1);
    }
    // W3F
    for (int i = t0; i < 4 * 8 * 25 * 2 * 32; i += S) {
        int rem = i;
        int lane = rem & 31; rem >>= 5;
        int s = rem & 1;     rem >>= 1;
        int t = rem % 25;    rem /= 25;
        int ks = rem & 7;
        int kc = rem >> 3;
        int gid = lane >> 2, tig = lane & 3;
        int n = 8 * t + gid;
        int k0 = 64 * kc + 8 * ks + tig;
        float h0, l0, h1, l1;
        split_tf32(W3[n * H2C + k0],     h0, l0);
        split_tf32(W3[n * H2C + k0 + 4], h1, l1);
        g_W3F[i] = s ? make_float2(l0, l1) : make_float2(h0, h1);
    }
    for (int e = t0; e < H3C * GDC; e += S) {
        int k = e / GDC, gd = e % GDC;
        g_WpT[e] = Wp[gd * H3C + k];
    }
}

// ----------------------------------------------- layer1 + layer2 (mma tf32)
// 128 rows/CTA, 256 thr (8 warps x 16 rows). Frag-ordered smem.
// smem: AfH 64KB, AfL 64KB, Bf 64KB  (192KB dynamic)
__global__ __launch_bounds__(256) void k_l12(const float* __restrict__ x0,
                                             const float* __restrict__ W1,
                                             const float* __restrict__ b1,
                                             const float* __restrict__ b2) {
    extern __shared__ float sm[];
    float* AfH = sm;            // [8w][16ks][32lane][4slot]
    float* AfL = sm + 16384;
    float* Bf  = sm + 32768;    // [16ks][8t][2s][32lane] float2 = 16384 floats
    __shared__ float xs[128 * 3], W1s[H1C * 3], b1s[H1C], b2s[H2C];

    const int tid = threadIdx.x;
    const int b0  = blockIdx.x * 128;
    const int w = tid >> 5, lane = tid & 31;
    const int gid = lane >> 2, tig = lane & 3;
    const int r0 = w * 16;

    for (int e = tid; e < H1C * 3; e += 256) W1s[e] = W1[e];
    if (tid < H1C) b1s[tid] = b1[tid];
    b2s[tid] = b2[tid];
    for (int e = tid; e < 128 * 3; e += 256) xs[e] = x0[(size_t)b0 * 3 + e];
    __syncthreads();

    // layer 1 -> split -> A fragment smem
    for (int e = tid; e < 128 * H1C; e += 256) {
        int r = e >> 7, k = e & 127;
        float v = fmaf(xs[r * 3 + 0], W1s[k * 3 + 0],
                  fmaf(xs[r * 3 + 1], W1s[k * 3 + 1],
                  fmaf(xs[r * 3 + 2], W1s[k * 3 + 2], b1s[k])));
        v = fmaxf(v, 0.f);
        float hi, lo; split_tf32(v, hi, lo);
        int fl, slot; frag_pos(r & 15, k & 7, fl, slot);
        int off = (((r >> 4) * 16 + (k >> 3)) * 32 + fl) * 4 + slot;
        AfH[off] = hi;
        AfL[off] = lo;
    }

    for (int p = 0; p < 4; p++) {
        __syncthreads();
        {
            float4* dst = (float4*)Bf;
            const float4* src = (const float4*)(g_W2F + (size_t)p * 8192);
            for (int e = tid; e < 4096; e += 256) dst[e] = src[e];
        }
        __syncthreads();

        float acc[8][4];
#pragma unroll
        for (int t = 0; t < 8; t++)
#pragma unroll
            for (int j = 0; j < 4; j++) acc[t][j] = 0.f;

#pragma unroll 4
        for (int ks = 0; ks < 16; ks++) {
            const float4 ah = *(const float4*)(AfH + ((w * 16 + ks) * 32 + lane) * 4);
            const float4 al = *(const float4*)(AfL + ((w * 16 + ks) * 32 + lane) * 4);
            uint32_t a0 = __float_as_uint(ah.x), a1 = __float_as_uint(ah.y);
            uint32_t a2 = __float_as_uint(ah.z), a3 = __float_as_uint(ah.w);
            uint32_t c0 = __float_as_uint(al.x), c1 = __float_as_uint(al.y);
            uint32_t c2 = __float_as_uint(al.z), c3 = __float_as_uint(al.w);
            float2 bh[8], bl[8];
#pragma unroll
            for (int t = 0; t < 8; t++) {
                const float2* bp = (const float2*)Bf + ((ks * 8 + t) * 2) * 32 + lane;
                bh[t] = bp[0];
                bl[t] = bp[32];
            }
#pragma unroll
            for (int t = 0; t < 8; t++)
                mma8(acc[t], a0, a1, a2, a3,
                     __float_as_uint(bh[t].x), __float_as_uint(bh[t].y));
#pragma unroll
            for (int t = 0; t < 8; t++)
                mma8(acc[t], a0, a1, a2, a3,
                     __float_as_uint(bl[t].x), __float_as_uint(bl[t].y));
#pragma unroll
            for (int t = 0; t < 8; t++)
                mma8(acc[t], c0, c1, c2, c3,
                     __float_as_uint(bh[t].x), __float_as_uint(bh[t].y));
        }

        // epilogue: h2 = relu(acc + b2) -> gmem fp32
#pragma unroll
        for (int t = 0; t < 8; t++) {
            int n = 64 * p + 8 * t + 2 * tig;
            float v0 = fmaxf(acc[t][0] + b2s[n],     0.f);
            float v1 = fmaxf(acc[t][1] + b2s[n + 1], 0.f);
            float v2 = fmaxf(acc[t][2] + b2s[n],     0.f);
            float v3 = fmaxf(acc[t][3] + b2s[n + 1], 0.f);
            *(float2*)(g_h2 + (size_t)(b0 + r0 + gid)     * H2C + n) = make_float2(v0, v1);
            *(float2*)(g_h2 + (size_t)(b0 + r0 + gid + 8) * H2C + n) = make_float2(v2, v3);
        }
    }
}

// ------------------------------------------------------- layer3 (mma tf32)
// 128 rows/CTA, 256 thr. K=256 in 4 chunks of 64; N=200 = 25 n-tiles.
// smem: AfH 32KB, AfL 32KB, Bf 100KB  (~164KB dynamic)
__global__ __launch_bounds__(256) void k_l3(const float* __restrict__ b3) {
    extern __shared__ float sm[];
    float* AfH = sm;            // [8w][8ks][32lane][4slot] = 8192 floats
    float* AfL = sm + 8192;
    float* Bf  = sm + 16384;    // [8ks][25t][2s][32lane] float2 = 25600 floats
    __shared__ float b3s[H3C];

    const int tid = threadIdx.x;
    const int b0  = blockIdx.x * 128;
    const int w = tid >> 5, lane = tid & 31;
    const int gid = lane >> 2, tig = lane & 3;
    const int r0 = w * 16;

    for (int e = tid; e < H3C; e += 256) b3s[e] = b3[e];

    float acc[25][4];
#pragma unroll
    for (int t = 0; t < 25; t++)
#pragma unroll
        for (int j = 0; j < 4; j++) acc[t][j] = 0.f;

    for (int kc = 0; kc < 4; kc++) {
        __syncthreads();
        // stage A chunk: rows 0..127, k in [64kc, 64kc+64)
        for (int e = tid; e < 128 * 16; e += 256) {
            int r = e >> 4, c4 = (e & 15) * 4;
            float4 v = *(const float4*)(g_h2 + (size_t)(b0 + r) * H2C + 64 * kc + c4);
            float vv[4] = {v.x, v.y, v.z, v.w};
#pragma unroll
            for (int j = 0; j < 4; j++) {
                int k = c4 + j;
                float hi, lo; split_tf32(vv[j], hi, lo);
                int fl, slot; frag_pos(r & 15, k & 7, fl, slot);
                int off = (((r >> 4) * 8 + (k >> 3)) * 32 + fl) * 4 + slot;
                AfH[off] = hi;
                AfL[off] = lo;
            }
        }
        {
            float4* dst = (float4*)Bf;
            const float4* src = (const float4*)(g_W3F + (size_t)kc * 12800);
            for (int e = tid; e < 6400; e += 256) dst[e] = src[e];
        }
        __syncthreads();

#pragma unroll 2
        for (int ks = 0; ks < 8; ks++) {
            const float4 ah = *(const float4*)(AfH + ((w * 8 + ks) * 32 + lane) * 4);
            const float4 al = *(const float4*)(AfL + ((w * 8 + ks) * 32 + lane) * 4);
            uint32_t a0 = __float_as_uint(ah.x), a1 = __float_as_uint(ah.y);
            uint32_t a2 = __float_as_uint(ah.z), a3 = __float_as_uint(ah.w);
            uint32_t c0 = __float_as_uint(al.x), c1 = __float_as_uint(al.y);
            uint32_t c2 = __float_as_uint(al.z), c3 = __float_as_uint(al.w);
#pragma unroll
            for (int t = 0; t < 25; t++) {
                const float2* bp = (const float2*)Bf + ((ks * 25 + t) * 2) * 32 + lane;
                float2 bh = bp[0], bl = bp[32];
                uint32_t b0r = __float_as_uint(bh.x), b1r = __float_as_uint(bh.y);
                uint32_t d0r = __float_as_uint(bl.x), d1r = __float_as_uint(bl.y);
                mma8(acc[t], a0, a1, a2, a3, b0r, b1r);
                mma8(acc[t], a0, a1, a2, a3, d0r, d1r);
                mma8(acc[t], c0, c1, c2, c3, b0r, b1r);
            }
        }
    }

    // epilogue: h3 = relu(acc + b3) -> gmem
#pragma unroll
    for (int t = 0; t < 25; t++) {
        int n = 8 * t + 2 * tig;
        float v0 = fmaxf(acc[t][0] + b3s[n],     0.f);
        float v1 = fmaxf(acc[t][1] + b3s[n + 1], 0.f);
        float v2 = fmaxf(acc[t][2] + b3s[n],     0.f);
        float v3 = fmaxf(acc[t][3] + b3s[n + 1], 0.f);
        *(float2*)(g_h3 + (size_t)(b0 + r0 + gid)     * H3C + n) = make_float2(v0, v1);
        *(float2*)(g_h3 + (size_t)(b0 + r0 + gid + 8) * H3C + n) = make_float2(v2, v3);
    }
}

// ------------------------------------------- heads + gumbel-argmax + out
// (unchanged from R4 — known-good ~950us; isolated from trunk experiment)
__global__ __launch_bounds__(256) void k_heads(
        const float* __restrict__ gumbel, const float* __restrict__ rnd,
        const float* __restrict__ Wmu,  const float* __restrict__ bmu,
        const float* __restrict__ Wsig, const float* __restrict__ bsig,
        const float* __restrict__ bpai, float* __restrict__ out) {
    extern __shared__ float sm[];
    float* h3s = sm;                    // [64][200]
    float* Wps = sm + 64 * H3C;         // [40][100] panel
    float* lps = Wps + 40 * GDC;        // [64][100]
    __shared__ float bps[GDC];
    __shared__ int   idxs[256];

    const int tid = threadIdx.x;
    const int b0  = blockIdx.x * 64;

    for (int e = tid; e < GDC; e += 256) bps[e] = bpai[e];
    {
        float4* dst = (float4*)h3s;
        const float4* src = (const float4*)(g_h3 + (size_t)b0 * H3C);
        for (int e = tid; e < 64 * H3C / 4; e += 256) dst[e] = src[e];
    }

    const int rt = tid & 7, ct = tid >> 3;
    const int r0 = rt * 8, c0 = ct * 4;
    const bool act = (ct < 25);
    float acc[8][4];
#pragma unroll
    for (int i = 0; i < 8; i++)
#pragma unroll
        for (int j = 0; j < 4; j++) acc[i][j] = 0.f;

    for (int p = 0; p < 5; p++) {
        __syncthreads();
        {
            float4* dst = (float4*)Wps;
            const float4* src = (const float4*)(g_WpT + p * 40 * GDC);
            for (int e = tid; e < 40 * GDC / 4; e += 256) dst[e] = src[e];
        }
        __syncthreads();
        if (act) {
            const int kb = p * 40;
            for (int k = 0; k < 40; k += 4) {
                float4 a[8];
#pragma unroll
                for (int i = 0; i < 8; i++)
                    a[i] = *(const float4*)(h3s + (r0 + i) * H3C + kb + k);
#pragma unroll
                for (int kk = 0; kk < 4; kk++) {
                    float4 bv = *(const float4*)(Wps + (k + kk) * GDC + c0);
#pragma unroll
                    for (int i = 0; i < 8; i++) {
                        float av = kk == 0 ? a[i].x : kk == 1 ? a[i].y
                                 : kk == 2 ? a[i].z : a[i].w;
                        acc[i][0] = fmaf(av, bv.x, acc[i][0]);
                        acc[i][1] = fmaf(av, bv.y, acc[i][1]);
                        acc[i][2] = fmaf(av, bv.z, acc[i][2]);
                        acc[i][3] = fmaf(av, bv.w, acc[i][3]);
                    }
                }
            }
        }
    }
    if (act) {
#pragma unroll
        for (int i = 0; i < 8; i++)
#pragma unroll
            for (int j = 0; j < 4; j++) {
                int gd = c0 + j;
                float pai = fabsf(acc[i][j] + bps[gd]);
                lps[(r0 + i) * GDC + gd] = logf(pai + 1e-12f);
            }
    }
    __syncthreads();

    {
        int r = tid >> 2, d = tid & 3;
        const float* gp = gumbel + (size_t)(b0 + r) * GDC + d;
        float best = -1e30f;
        int bg = 0;
#pragma unroll
        for (int g = 0; g < GC; g++) {
            float v = lps[r * GDC + g * 4 + d] + gp[g * 4];
            if (v > best) { best = v; bg = g; }
        }
        idxs[tid] = bg;
    }
    __syncthreads();

    const int wid = tid >> 5, lane = tid & 31;
    for (int q = 0; q < 32; q++) {
        int p = wid * 32 + q;
        int r = p >> 2, d = p & 3;
        int head = idxs[p] * 4 + d;
        const float4* wm = (const float4*)(Wmu  + (size_t)head * H3C);
        const float4* ws = (const float4*)(Wsig + (size_t)head * H3C);
        const float4* hv = (const float4*)(h3s + r * H3C);

        float4 h0 = hv[lane];
        float4 m0 = wm[lane];
        float4 s0 = ws[lane];
        float smu = h0.x * m0.x + h0.y * m0.y + h0.z * m0.z + h0.w * m0.w;
        float ssg = h0.x * s0.x + h0.y * s0.y + h0.z * s0.z + h0.w * s0.w;
        if (lane < 18) {
            float4 h1v = hv[32 + lane];
            float4 m1  = wm[32 + lane];
            float4 s1  = ws[32 + lane];
            smu += h1v.x * m1.x + h1v.y * m1.y + h1v.z * m1.z + h1v.w * m1.w;
            ssg += h1v.x * s1.x + h1v.y * s1.y + h1v.z * s1.z + h1v.w * s1.w;
        }
#pragma unroll
        for (int off = 16; off > 0; off >>= 1) {
            smu += __shfl_xor_sync(0xffffffffu, smu, off);
            ssg += __shfl_xor_sync(0xffffffffu, ssg, off);
        }
        if (lane == 0) {
            float mu = smu + bmu[head];
            float sg = fabsf(ssg + bsig[head]);
            size_t oi = (size_t)(b0 + r) * DC + d;
            out[oi] = rnd[oi] * sg + mu;
        }
    }
}

// ---------------------------------------------------------------- launch
extern "C" void kernel_launch(void* const* d_in, const int* in_sizes, int n_in,
                              void* d_out, int out_size) {
    const float* x0   = (const float*)d_in[0];
    const float* rnd  = (const float*)d_in[1];
    const float* gum  = (const float*)d_in[2];
    const float* W1   = (const float*)d_in[3];
    const float* b1   = (const float*)d_in[4];
    const float* W2   = (const float*)d_in[5];
    const float* b2   = (const float*)d_in[6];
    const float* W3   = (const float*)d_in[7];
    const float* b3   = (const float*)d_in[8];
    const float* Wmu  = (const float*)d_in[9];
    const float* bmu  = (const float*)d_in[10];
    const float* Wsig = (const float*)d_in[11];
    const float* bsig = (const float*)d_in[12];
    const float* Wpai = (const float*)d_in[13];
    const float* bpai = (const float*)d_in[14];
    float* out = (float*)d_out;

    const size_t smA = 49152 * sizeof(float);                                 // 192KB
    const size_t smB = 41984 * sizeof(float);                                 // 164KB
    const size_t smC = (size_t)(64 * H3C + 40 * GDC + 64 * GDC) * sizeof(float); // ~93KB

    cudaFuncSetAttribute(k_l12,   cudaFuncAttributeMaxDynamicSharedMemorySize, (int)smA);
    cudaFuncSetAttribute(k_l3,    cudaFuncAttributeMaxDynamicSharedMemorySize, (int)smB);
    cudaFuncSetAttribute(k_heads, cudaFuncAttributeMaxDynamicSharedMemorySize, (int)smC);

    k_prep <<<256, 256>>>(W2, W3, Wpai);
    k_l12  <<<NB / 128, 256, smA>>>(x0, W1, b1, b2);
    k_l3   <<<NB / 128, 256, smB>>>(b3);
    k_heads<<<NB / 64, 256, smC>>>(gum, rnd, Wmu, bmu, Wsig, bsig, bpai, out);
}

// round 7
// speedup vs baseline: 1.4240x; 1.3396x over previous
#include <cuda_runtime.h>
#include <math.h>
#include <stdint.h>

#define NB   262144
#define H1C  128
#define H2C  256
#define H3C  200
#define GC   25
#define DC   4
#define GDC  100

// ---------------------------------------------------------- device scratch
__device__ float g_h2 [(size_t)NB * H2C];
__device__ float g_h3 [(size_t)NB * H3C];
__device__ float g_W2T[H1C * H2C];          // [k][n]
__device__ float g_W3T[H2C * H3C];          // [k][n]
__device__ float g_WpT[H3C * GDC];          // [k][g*4+d]

// ------------------------------------------------------------ f32x2 helpers
__device__ __forceinline__ uint64_t pk2(float x, float y) {
    uint64_t r;
    asm("mov.b64 %0, {%1, %2};" : "=l"(r) : "f"(x), "f"(y));
    return r;
}
__device__ __forceinline__ float2 upk2(uint64_t v) {
    float2 r;
    asm("mov.b64 {%0, %1}, %2;" : "=f"(r.x), "=f"(r.y) : "l"(v));
    return r;
}
__device__ __forceinline__ void fma2(uint64_t& d, uint64_t a, uint64_t b) {
    asm("fma.rn.f32x2 %0, %1, %2, %0;" : "+l"(d) : "l"(a), "l"(b));
}

// ------------------------------------------------------------------- prep
__global__ void k_prep(const float* __restrict__ W2, const float* __restrict__ W3,
                       const float* __restrict__ Wp) {
    int stride = gridDim.x * blockDim.x;
    int i0 = blockIdx.x * blockDim.x + threadIdx.x;
    for (int e = i0; e < H1C * H2C; e += stride) {
        int k = e / H2C, n = e % H2C;
        g_W2T[e] = W2[n * H1C + k];
    }
    for (int e = i0; e < H2C * H3C; e += stride) {
        int k = e / H3C, n = e % H3C;
        g_W3T[e] = W3[n * H2C + k];
    }
    for (int e = i0; e < H3C * GDC; e += stride) {
        int k = e / GDC, gd = e % GDC;
        g_WpT[e] = Wp[gd * H3C + k];
    }
}

// ------------------------------------------- layer1 + layer2 (FFMA2)
// 64 rows/CTA, 256 thr; warp = 8 rows (A broadcast), lane = 8 cols.
// smem: h1s[64][128] 32KB + W2s[64][256] 64KB panel -> 96KB, 2 CTA/SM.
__global__ __launch_bounds__(256, 2) void k_l12(const float* __restrict__ x0,
                                                const float* __restrict__ W1,
                                                const float* __restrict__ b1,
                                                const float* __restrict__ b2) {
    extern __shared__ float sm[];
    float* h1s = sm;                 // [64][128]
    float* W2s = sm + 64 * H1C;      // [64][256] k-panel
    __shared__ float xs[64 * 3], W1s[H1C * 3], b1s[H1C], b2s[H2C];

    const int tid = threadIdx.x;
    const int b0  = blockIdx.x * 64;
    const int tx = tid & 31, ty = tid >> 5;
    const int r0 = ty * 8, c0 = tx * 8;

    for (int e = tid; e < H1C * 3; e += 256) W1s[e] = W1[e];
    if (tid < H1C) b1s[tid] = b1[tid];
    b2s[tid] = b2[tid];
    for (int e = tid; e < 64 * 3; e += 256) xs[e] = x0[(size_t)b0 * 3 + e];
    __syncthreads();

    // layer 1
    for (int e = tid; e < 64 * H1C; e += 256) {
        int r = e >> 7, j = e & 127;
        float v = fmaf(xs[r * 3 + 0], W1s[j * 3 + 0],
                  fmaf(xs[r * 3 + 1], W1s[j * 3 + 1],
                  fmaf(xs[r * 3 + 2], W1s[j * 3 + 2], b1s[j])));
        h1s[e] = fmaxf(v, 0.f);
    }

    uint64_t acc[8][4];
#pragma unroll
    for (int i = 0; i < 8; i++)
#pragma unroll
        for (int j = 0; j < 4; j++) acc[i][j] = 0ull;

    for (int p = 0; p < 2; p++) {
        __syncthreads();   // h1s ready (p=0) / previous mainloop done
        {
            float4* dst = (float4*)W2s;
            const float4* src = (const float4*)(g_W2T + p * 64 * H2C);
            for (int e = tid; e < 64 * H2C / 4; e += 256) dst[e] = src[e];
        }
        __syncthreads();
        const int kb = p * 64;
#pragma unroll 4
        for (int k = 0; k < 64; k++) {
            const uint64_t* bp = (const uint64_t*)(W2s + k * H2C + c0);
            uint64_t bv0 = bp[0], bv1 = bp[1], bv2 = bp[2], bv3 = bp[3];
#pragma unroll
            for (int i = 0; i < 8; i++) {
                float av = h1s[(r0 + i) * H1C + kb + k];   // warp-uniform bcast
                uint64_t a2 = pk2(av, av);
                fma2(acc[i][0], a2, bv0);
                fma2(acc[i][1], a2, bv1);
                fma2(acc[i][2], a2, bv2);
                fma2(acc[i][3], a2, bv3);
            }
        }
    }

    // epilogue: h2 = relu(acc + b2)
#pragma unroll
    for (int i = 0; i < 8; i++) {
        float* dst = g_h2 + (size_t)(b0 + r0 + i) * H2C + c0;
#pragma unroll
        for (int j = 0; j < 4; j++) {
            float2 v = upk2(acc[i][j]);
            int n = c0 + 2 * j;
            v.x = fmaxf(v.x + b2s[n],     0.f);
            v.y = fmaxf(v.y + b2s[n + 1], 0.f);
            *(float2*)(dst + 2 * j) = v;
        }
    }
}

// --------------------------------------------------------- layer3 (FFMA2)
// 128 rows/CTA, 400 thr (16 row-thr x 25 col-thr), all lanes active.
// smem: h2s[128][260] 133120B + W3s[64][200] 51200B = 184320B.
__global__ __launch_bounds__(400) void k_l3(const float* __restrict__ b3) {
    extern __shared__ float sm[];
    float* h2s = sm;                 // [128][260] padded
    float* W3s = sm + 128 * 260;     // [64][200] k-panel
    __shared__ float b3s[H3C];

    const int tid = threadIdx.x;
    const int b0  = blockIdx.x * 128;
    const int ct = tid % 25, rt = tid / 25;   // rt in [0,16)
    const int r0 = rt * 8, c0 = ct * 8;

    for (int e = tid; e < H3C; e += 400) b3s[e] = b3[e];
    // stage h2 tile (padded rows)
    for (int e = tid; e < 128 * 64; e += 400) {
        int r = e >> 6, c4 = (e & 63) * 4;
        *(float4*)(h2s + r * 260 + c4) =
            *(const float4*)(g_h2 + (size_t)(b0 + r) * H2C + c4);
    }

    uint64_t acc[8][4];
#pragma unroll
    for (int i = 0; i < 8; i++)
#pragma unroll
        for (int j = 0; j < 4; j++) acc[i][j] = 0ull;

    for (int kp = 0; kp < 4; kp++) {
        __syncthreads();   // h2s staged (kp=0) / prev mainloop done
        {
            float4* dst = (float4*)W3s;
            const float4* src = (const float4*)(g_W3T + kp * 64 * H3C);
            for (int e = tid; e < 64 * H3C / 4; e += 400) dst[e] = src[e];
        }
        __syncthreads();
        const int kb = kp * 64;
#pragma unroll 4
        for (int k = 0; k < 64; k++) {
            const uint64_t* bp = (const uint64_t*)(W3s + k * H3C + c0);
            uint64_t bv0 = bp[0], bv1 = bp[1], bv2 = bp[2], bv3 = bp[3];
#pragma unroll
            for (int i = 0; i < 8; i++) {
                float av = h2s[(r0 + i) * 260 + kb + k];
                uint64_t a2 = pk2(av, av);
                fma2(acc[i][0], a2, bv0);
                fma2(acc[i][1], a2, bv1);
                fma2(acc[i][2], a2, bv2);
                fma2(acc[i][3], a2, bv3);
            }
        }
    }

    // epilogue: h3 = relu(acc + b3)
#pragma unroll
    for (int i = 0; i < 8; i++) {
        float* dst = g_h3 + (size_t)(b0 + r0 + i) * H3C + c0;
#pragma unroll
        for (int j = 0; j < 4; j++) {
            float2 v = upk2(acc[i][j]);
            int n = c0 + 2 * j;
            v.x = fmaxf(v.x + b3s[n],     0.f);
            v.y = fmaxf(v.y + b3s[n + 1], 0.f);
            *(float2*)(dst + 2 * j) = v;
        }
    }
}

// ------------------------------------------- heads + gumbel-argmax + out
// 64 rows/CTA, 256 thr. pi GEMM: warp = 8 rows (A broadcast), lane = 4 cols
// (lanes 0..24 active). Wp in five 40-k panels -> ~94KB smem -> 2 CTA/SM.
__global__ __launch_bounds__(256) void k_heads(
        const float* __restrict__ gumbel, const float* __restrict__ rnd,
        const float* __restrict__ Wmu,  const float* __restrict__ bmu,
        const float* __restrict__ Wsig, const float* __restrict__ bsig,
        const float* __restrict__ bpai, float* __restrict__ out) {
    extern __shared__ float sm[];
    float* h3s = sm;                    // [64][204] padded
    float* Wps = sm + 64 * 204;         // [40][100] k-panel
    float* lps = Wps + 40 * GDC;        // [64][100]
    __shared__ float bps[GDC];
    __shared__ int   idxs[256];

    const int tid = threadIdx.x;
    const int b0  = blockIdx.x * 64;
    const int wid = tid >> 5, lane = tid & 31;
    const int r0 = wid * 8, c0 = lane * 4;
    const bool act = (lane < 25);

    for (int e = tid; e < GDC; e += 256) bps[e] = bpai[e];
    // stage h3 tile (padded rows, float4)
    for (int e = tid; e < 64 * 50; e += 256) {
        int r = e / 50, c4 = (e % 50) * 4;
        *(float4*)(h3s + r * 204 + c4) =
            *(const float4*)(g_h3 + (size_t)(b0 + r) * H3C + c4);
    }

    uint64_t acc[8][2];
#pragma unroll
    for (int i = 0; i < 8; i++) { acc[i][0] = 0ull; acc[i][1] = 0ull; }

    for (int p = 0; p < 5; p++) {
        __syncthreads();   // h3s staged (p=0) / prev mainloop done
        {
            float4* dst = (float4*)Wps;
            const float4* src = (const float4*)(g_WpT + p * 40 * GDC);
            for (int e = tid; e < 40 * GDC / 4; e += 256) dst[e] = src[e];
        }
        __syncthreads();
        if (act) {
            const int kb = p * 40;
#pragma unroll 4
            for (int k = 0; k < 40; k++) {
                const uint64_t* bp = (const uint64_t*)(Wps + k * GDC + c0);
                uint64_t bv0 = bp[0], bv1 = bp[1];
#pragma unroll
                for (int i = 0; i < 8; i++) {
                    float av = h3s[(r0 + i) * 204 + kb + k];  // warp-uniform
                    uint64_t a2 = pk2(av, av);
                    fma2(acc[i][0], a2, bv0);
                    fma2(acc[i][1], a2, bv1);
                }
            }
        }
    }
    if (act) {
#pragma unroll
        for (int i = 0; i < 8; i++) {
            float2 v0 = upk2(acc[i][0]);
            float2 v1 = upk2(acc[i][1]);
            float4 o;
            o.x = logf(fabsf(v0.x + bps[c0])     + 1e-12f);
            o.y = logf(fabsf(v0.y + bps[c0 + 1]) + 1e-12f);
            o.z = logf(fabsf(v1.x + bps[c0 + 2]) + 1e-12f);
            o.w = logf(fabsf(v1.y + bps[c0 + 3]) + 1e-12f);
            *(float4*)(lps + (r0 + i) * GDC + c0) = o;
        }
    }
    __syncthreads();

    // Gumbel-argmax per (row, d)
    {
        int r = tid >> 2, d = tid & 3;
        const float* gp = gumbel + (size_t)(b0 + r) * GDC + d;
        float best = -1e30f;
        int bg = 0;
#pragma unroll
        for (int g = 0; g < GC; g++) {
            float v = lps[r * GDC + g * 4 + d] + gp[g * 4];
            if (v > best) { best = v; bg = g; }
        }
        idxs[tid] = bg;
    }
    __syncthreads();

    // Selected mu / sigma: warp-cooperative (coalesced row walks)
    for (int q = 0; q < 32; q++) {
        int pp = wid * 32 + q;
        int r = pp >> 2, d = pp & 3;
        int head = idxs[pp] * 4 + d;
        const float4* wm = (const float4*)(Wmu  + (size_t)head * H3C);
        const float4* ws = (const float4*)(Wsig + (size_t)head * H3C);
        const float4* hv = (const float4*)(h3s + r * 204);

        float4 h0 = hv[lane];
        float4 m0 = wm[lane];
        float4 s0 = ws[lane];
        float smu = h0.x * m0.x + h0.y * m0.y + h0.z * m0.z + h0.w * m0.w;
        float ssg = h0.x * s0.x + h0.y * s0.y + h0.z * s0.z + h0.w * s0.w;
        if (lane < 18) {
            float4 h1v = hv[32 + lane];
            float4 m1  = wm[32 + lane];
            float4 s1  = ws[32 + lane];
            smu += h1v.x * m1.x + h1v.y * m1.y + h1v.z * m1.z + h1v.w * m1.w;
            ssg += h1v.x * s1.x + h1v.y * s1.y + h1v.z * s1.z + h1v.w * s1.w;
        }
#pragma unroll
        for (int off = 16; off > 0; off >>= 1) {
            smu += __shfl_xor_sync(0xffffffffu, smu, off);
            ssg += __shfl_xor_sync(0xffffffffu, ssg, off);
        }
        if (lane == 0) {
            float mu = smu + bmu[head];
            float sg = fabsf(ssg + bsig[head]);
            size_t oi = (size_t)(b0 + r) * DC + d;
            out[oi] = rnd[oi] * sg + mu;
        }
    }
}

// ---------------------------------------------------------------- launch
extern "C" void kernel_launch(void* const* d_in, const int* in_sizes, int n_in,
                              void* d_out, int out_size) {
    const float* x0   = (const float*)d_in[0];
    const float* rnd  = (const float*)d_in[1];
    const float* gum  = (const float*)d_in[2];
    const float* W1   = (const float*)d_in[3];
    const float* b1   = (const float*)d_in[4];
    const float* W2   = (const float*)d_in[5];
    const float* b2   = (const float*)d_in[6];
    const float* W3   = (const float*)d_in[7];
    const float* b3   = (const float*)d_in[8];
    const float* Wmu  = (const float*)d_in[9];
    const float* bmu  = (const float*)d_in[10];
    const float* Wsig = (const float*)d_in[11];
    const float* bsig = (const float*)d_in[12];
    const float* Wpai = (const float*)d_in[13];
    const float* bpai = (const float*)d_in[14];
    float* out = (float*)d_out;

    const size_t smA = (size_t)(64 * H1C + 64 * H2C) * sizeof(float);        //  96KB
    const size_t smB = (size_t)(128 * 260 + 64 * H3C) * sizeof(float);       // 180KB
    const size_t smC = (size_t)(64 * 204 + 40 * GDC + 64 * GDC) * sizeof(float); // ~92KB

    cudaFuncSetAttribute(k_l12,   cudaFuncAttributeMaxDynamicSharedMemorySize, (int)smA);
    cudaFuncSetAttribute(k_l3,    cudaFuncAttributeMaxDynamicSharedMemorySize, (int)smB);
    cudaFuncSetAttribute(k_heads, cudaFuncAttributeMaxDynamicSharedMemorySize, (int)smC);

    k_prep <<<64, 256>>>(W2, W3, Wpai);
    k_l12  <<<NB / 64, 256, smA>>>(x0, W1, b1, b2);
    k_l3   <<<NB / 128, 400, smB>>>(b3);
    k_heads<<<NB / 64, 256, smC>>>(gum, rnd, Wmu, bmu, Wsig, bsig, bpai, out);
}

// round 8
// speedup vs baseline: 1.7229x; 1.2099x over previous
#include <cuda_runtime.h>
#include <math.h>
#include <stdint.h>

#define NB   262144
#define H1C  128
#define H2C  256
#define H3C  200
#define GC   25
#define DC   4
#define GDC  100

// ---------------------------------------------------------- device scratch
__device__ float g_W2T[128 * 256];      // [k][n]           (128KB)
__device__ float g_W3T[256 * 208];      // [k][n], n padded 200->208
__device__ float g_WpT[200 * 104];      // [k][n], n padded 100->104

// ------------------------------------------------------------ f32x2 helpers
__device__ __forceinline__ uint64_t pk2(float x, float y) {
    uint64_t r;
    asm("mov.b64 %0, {%1, %2};" : "=l"(r) : "f"(x), "f"(y));
    return r;
}
__device__ __forceinline__ float2 upk2(uint64_t v) {
    float2 r;
    asm("mov.b64 {%0, %1}, %2;" : "=f"(r.x), "=f"(r.y) : "l"(v));
    return r;
}
__device__ __forceinline__ void fma2(uint64_t& d, uint64_t a, uint64_t b) {
    asm("fma.rn.f32x2 %0, %1, %2, %0;" : "+l"(d) : "l"(a), "l"(b));
}

// ------------------------------------------------------------------- prep
__global__ void k_prep(const float* __restrict__ W2, const float* __restrict__ W3,
                       const float* __restrict__ Wp) {
    int stride = gridDim.x * blockDim.x;
    int i0 = blockIdx.x * blockDim.x + threadIdx.x;
    for (int e = i0; e < 128 * 256; e += stride) {
        int k = e >> 8, n = e & 255;
        g_W2T[e] = W2[n * H1C + k];
    }
    for (int e = i0; e < 256 * 208; e += stride) {
        int k = e / 208, n = e % 208;
        g_W3T[e] = (n < 200) ? W3[n * H2C + k] : 0.f;
    }
    for (int e = i0; e < 200 * 104; e += stride) {
        int k = e / 104, n = e % 104;
        g_WpT[e] = (n < 100) ? Wp[n * H3C + k] : 0.f;
    }
}

// ------------------------------------------------------------- fused kernel
// 64 rows per CTA, 256 threads (8 warps x 8 rows). All GEMMs FFMA2 with
// conflict-free lane mapping n = 64j + 2*lane. Activations stay in smem.
__global__ __launch_bounds__(256, 2) void k_fused(
        const float* __restrict__ x0,   const float* __restrict__ W1,
        const float* __restrict__ b1,   const float* __restrict__ b2,
        const float* __restrict__ b3,
        const float* __restrict__ gumbel, const float* __restrict__ rnd,
        const float* __restrict__ Wmu,  const float* __restrict__ bmu,
        const float* __restrict__ Wsig, const float* __restrict__ bsig,
        const float* __restrict__ bpai, float* __restrict__ out) {
    extern __shared__ float sm[];
    float* h1s = sm;              // [64][128]            @ [0, 8192)
    float* W2s = sm + 8192;       // [64][256] k-panel    @ [8192, 24576)
    float* h2s = sm;              // [64][256] overlay    @ [0, 16384)
    float* W3s = sm + 16384;      // [32][208] k-panel    @ [16384, 23040)
    float* h3s = sm;              // [64][200] overlay    @ [0, 12800)
    float* Wps = sm + 16384;      // [40][104] k-panel    @ [16384, 20544)
    float* lps = sm + 20544;      // [64][100]            @ [20544, 26944)
    __shared__ float xs[64 * 3], W1s[H1C * 3], b1s[H1C], b2s[H2C], b3s[H3C], bps[GDC];
    __shared__ int idxs[256];

    const int tid  = threadIdx.x;
    const int wid  = tid >> 5, lane = tid & 31;
    const int b0   = blockIdx.x * 64;
    const int r0   = wid * 8;

    // ---- stage constants + W2 panel 0
    for (int e = tid; e < H1C * 3; e += 256) W1s[e] = W1[e];
    if (tid < H1C) b1s[tid] = b1[tid];
    b2s[tid] = b2[tid];
    for (int e = tid; e < H3C; e += 256) b3s[e] = b3[e];
    for (int e = tid; e < GDC; e += 256) bps[e] = bpai[e];
    for (int e = tid; e < 64 * 3; e += 256) xs[e] = x0[(size_t)b0 * 3 + e];
    {
        float4* dst = (float4*)W2s;
        const float4* src = (const float4*)g_W2T;
        for (int e = tid; e < 4096; e += 256) dst[e] = src[e];
    }
    __syncthreads();

    // ---- layer 1: h1 = relu(x0 @ W1^T + b1)
    for (int e = tid; e < 64 * H1C; e += 256) {
        int r = e >> 7, j = e & 127;
        float v = fmaf(xs[r * 3 + 0], W1s[j * 3 + 0],
                  fmaf(xs[r * 3 + 1], W1s[j * 3 + 1],
                  fmaf(xs[r * 3 + 2], W1s[j * 3 + 2], b1s[j])));
        h1s[e] = fmaxf(v, 0.f);
    }
    __syncthreads();

    // ---- layer 2 GEMM: [64 x 256], K=128 in two 64-k panels
    uint64_t a2acc[8][4];
#pragma unroll
    for (int i = 0; i < 8; i++)
#pragma unroll
        for (int j = 0; j < 4; j++) a2acc[i][j] = 0ull;

    for (int p = 0; p < 2; p++) {
        if (p == 1) {
            __syncthreads();
            float4* dst = (float4*)W2s;
            const float4* src = (const float4*)(g_W2T + 16384);
            for (int e = tid; e < 4096; e += 256) dst[e] = src[e];
            __syncthreads();
        }
        const int kb = p * 64;
#pragma unroll 4
        for (int k = 0; k < 64; k++) {
            const uint64_t* bp = (const uint64_t*)(W2s + k * 256);
            uint64_t bv0 = bp[lane], bv1 = bp[32 + lane];
            uint64_t bv2 = bp[64 + lane], bv3 = bp[96 + lane];
#pragma unroll
            for (int i = 0; i < 8; i++) {
                float av = h1s[(r0 + i) * H1C + kb + k];
                uint64_t a2 = pk2(av, av);
                fma2(a2acc[i][0], a2, bv0);
                fma2(a2acc[i][1], a2, bv1);
                fma2(a2acc[i][2], a2, bv2);
                fma2(a2acc[i][3], a2, bv3);
            }
        }
    }
    __syncthreads();   // done reading h1s/W2s before h2s overlay

    // epilogue: h2s = relu(acc + b2); cols n = 64j + 2*lane
#pragma unroll
    for (int i = 0; i < 8; i++)
#pragma unroll
        for (int j = 0; j < 4; j++) {
            int n = 64 * j + 2 * lane;
            float2 v = upk2(a2acc[i][j]);
            v.x = fmaxf(v.x + b2s[n],     0.f);
            v.y = fmaxf(v.y + b2s[n + 1], 0.f);
            *(float2*)(h2s + (r0 + i) * 256 + n) = v;
        }
    __syncthreads();

    // ---- layer 3 GEMM: [64 x 200(208)], K=256 in eight 32-k panels
    uint64_t a3acc[8][4];
#pragma unroll
    for (int i = 0; i < 8; i++)
#pragma unroll
        for (int j = 0; j < 4; j++) a3acc[i][j] = 0ull;

    for (int kp = 0; kp < 8; kp++) {
        {
            float4* dst = (float4*)W3s;
            const float4* src = (const float4*)(g_W3T + kp * 32 * 208);
            for (int e = tid; e < 1664; e += 256) dst[e] = src[e];
        }
        __syncthreads();
#pragma unroll 4
        for (int k = 0; k < 32; k++) {
            const uint64_t* bp = (const uint64_t*)(W3s + k * 208);
            uint64_t bv0 = bp[lane], bv1 = bp[32 + lane], bv2 = bp[64 + lane];
            uint64_t bv3 = (lane < 8) ? bp[96 + lane] : 0ull;
#pragma unroll
            for (int i = 0; i < 8; i++) {
                float av = h2s[(r0 + i) * 256 + kp * 32 + k];
                uint64_t a2 = pk2(av, av);
                fma2(a3acc[i][0], a2, bv0);
                fma2(a3acc[i][1], a2, bv1);
                fma2(a3acc[i][2], a2, bv2);
                fma2(a3acc[i][3], a2, bv3);
            }
        }
        __syncthreads();
    }

    // epilogue: h3s = relu(acc + b3) (overlays h2s)
#pragma unroll
    for (int i = 0; i < 8; i++) {
#pragma unroll
        for (int j = 0; j < 3; j++) {
            int n = 64 * j + 2 * lane;
            float2 v = upk2(a3acc[i][j]);
            v.x = fmaxf(v.x + b3s[n],     0.f);
            v.y = fmaxf(v.y + b3s[n + 1], 0.f);
            *(float2*)(h3s + (r0 + i) * 200 + n) = v;
        }
        if (lane < 4) {
            int n = 192 + 2 * lane;
            float2 v = upk2(a3acc[i][3]);
            v.x = fmaxf(v.x + b3s[n],     0.f);
            v.y = fmaxf(v.y + b3s[n + 1], 0.f);
            *(float2*)(h3s + (r0 + i) * 200 + n) = v;
        }
    }
    __syncthreads();

    // ---- pi GEMM: [64 x 100(104)], K=200 in five 40-k panels
    uint64_t apacc[8][2];
#pragma unroll
    for (int i = 0; i < 8; i++) { apacc[i][0] = 0ull; apacc[i][1] = 0ull; }

    for (int p = 0; p < 5; p++) {
        {
            float4* dst = (float4*)Wps;
            const float4* src = (const float4*)(g_WpT + p * 40 * 104);
            for (int e = tid; e < 1040; e += 256) dst[e] = src[e];
        }
        __syncthreads();
#pragma unroll 4
        for (int k = 0; k < 40; k++) {
            const uint64_t* bp = (const uint64_t*)(Wps + k * 104);
            uint64_t bv0 = bp[lane];
            uint64_t bv1 = (lane < 18) ? bp[32 + lane] : 0ull;
#pragma unroll
            for (int i = 0; i < 8; i++) {
                float av = h3s[(r0 + i) * 200 + p * 40 + k];
                uint64_t a2 = pk2(av, av);
                fma2(apacc[i][0], a2, bv0);
                fma2(apacc[i][1], a2, bv1);
            }
        }
        __syncthreads();
    }

    // lps = log(|pi + b| + eps)
#pragma unroll
    for (int i = 0; i < 8; i++) {
        int n = 2 * lane;
        float2 v = upk2(apacc[i][0]);
        float2 o;
        o.x = logf(fabsf(v.x + bps[n])     + 1e-12f);
        o.y = logf(fabsf(v.y + bps[n + 1]) + 1e-12f);
        *(float2*)(lps + (r0 + i) * GDC + n) = o;
        if (lane < 18) {
            int m = 64 + 2 * lane;
            float2 w = upk2(apacc[i][1]);
            float2 q;
            q.x = logf(fabsf(w.x + bps[m])     + 1e-12f);
            q.y = logf(fabsf(w.y + bps[m + 1]) + 1e-12f);
            *(float2*)(lps + (r0 + i) * GDC + m) = q;
        }
    }
    __syncthreads();

    // ---- Gumbel-argmax per (row, d)
    {
        int r = tid >> 2, d = tid & 3;
        const float* gp = gumbel + (size_t)(b0 + r) * GDC + d;
        float best = -1e30f;
        int bg = 0;
#pragma unroll
        for (int g = 0; g < GC; g++) {
            float v = lps[r * GDC + g * 4 + d] + gp[g * 4];
            if (v > best) { best = v; bg = g; }
        }
        idxs[tid] = bg;
    }
    __syncthreads();

    // ---- selection: 8 lanes per pair, 4 pairs per warp per iteration
    const int sl = lane & 7, grp = lane >> 3;
    for (int it = 0; it < 8; it++) {
        int pp = wid * 32 + it * 4 + grp;        // pair index in [0,256)
        int r = pp >> 2, d = pp & 3;
        int head = idxs[pp] * 4 + d;
        const float4* wm = (const float4*)(Wmu  + (size_t)head * H3C);
        const float4* ws = (const float4*)(Wsig + (size_t)head * H3C);
        const float4* hv = (const float4*)(h3s + r * H3C);

        float smu = 0.f, ssg = 0.f;
#pragma unroll
        for (int j = 0; j < 6; j++) {
            int i4 = sl + 8 * j;
            float4 h = hv[i4];
            float4 m = wm[i4];
            float4 s = ws[i4];
            smu = fmaf(h.x, m.x, fmaf(h.y, m.y, fmaf(h.z, m.z, fmaf(h.w, m.w, smu))));
            ssg = fmaf(h.x, s.x, fmaf(h.y, s.y, fmaf(h.z, s.z, fmaf(h.w, s.w, ssg))));
        }
        if (sl < 2) {
            int i4 = 48 + sl;
            float4 h = hv[i4];
            float4 m = wm[i4];
            float4 s = ws[i4];
            smu = fmaf(h.x, m.x, fmaf(h.y, m.y, fmaf(h.z, m.z, fmaf(h.w, m.w, smu))));
            ssg = fmaf(h.x, s.x, fmaf(h.y, s.y, fmaf(h.z, s.z, fmaf(h.w, s.w, ssg))));
        }
#pragma unroll
        for (int off = 4; off > 0; off >>= 1) {
            smu += __shfl_xor_sync(0xffffffffu, smu, off);
            ssg += __shfl_xor_sync(0xffffffffu, ssg, off);
        }
        if (sl == 0) {
            float mu = smu + bmu[head];
            float sg = fabsf(ssg + bsig[head]);
            size_t oi = (size_t)(b0 + r) * DC + d;
            out[oi] = rnd[oi] * sg + mu;
        }
    }
}

// ---------------------------------------------------------------- launch
extern "C" void kernel_launch(void* const* d_in, const int* in_sizes, int n_in,
                              void* d_out, int out_size) {
    const float* x0   = (const float*)d_in[0];
    const float* rnd  = (const float*)d_in[1];
    const float* gum  = (const float*)d_in[2];
    const float* W1   = (const float*)d_in[3];
    const float* b1   = (const float*)d_in[4];
    const float* W2   = (const float*)d_in[5];
    const float* b2   = (const float*)d_in[6];
    const float* W3   = (const float*)d_in[7];
    const float* b3   = (const float*)d_in[8];
    const float* Wmu  = (const float*)d_in[9];
    const float* bmu  = (const float*)d_in[10];
    const float* Wsig = (const float*)d_in[11];
    const float* bsig = (const float*)d_in[12];
    const float* Wpai = (const float*)d_in[13];
    const float* bpai = (const float*)d_in[14];
    float* out = (float*)d_out;

    const size_t smF = 26944 * sizeof(float);   // 107776 B

    cudaFuncSetAttribute(k_fused, cudaFuncAttributeMaxDynamicSharedMemorySize, (int)smF);

    k_prep <<<64, 256>>>(W2, W3, Wpai);
    k_fused<<<NB / 64, 256, smF>>>(x0, W1, b1, b2, b3,
                                   gum, rnd, Wmu, bmu, Wsig, bsig, bpai, out);
}